// round 12
// baseline (speedup 1.0000x reference)
#include <cuda_runtime.h>
#include <cstdint>

#define BB   128
#define TT   2048
#define DD   64
#define HH   256
#define OO   32
#define NBLK 128
#define NTHR 256

// ---- static device scratch (no allocations) ----
__device__ float    g_P[(size_t)TT * BB * 1024];          // [t][blk=bg*16+cg][b16*64+l] (1 GiB)
__device__ float    g_hist[(size_t)(TT + 1) * BB * HH];   // [t][b][k]
__device__ unsigned g_flag[NBLK * 32];                    // one flag per block, 128B apart

__global__ void reset_kernel() {
    for (int i = threadIdx.x; i < NBLK * 32; i += 256) g_flag[i] = 0u;
}

__device__ __forceinline__ float sigf(float x) {
    return 1.0f / (1.0f + __expf(-x));
}
__device__ __forceinline__ float tanh_fast(float x) {
    return 1.0f - 2.0f / (__expf(2.0f * x) + 1.0f);
}

__device__ __forceinline__ void fma2(uint64_t& acc, uint64_t a, uint64_t b) {
    asm("fma.rn.f32x2 %0, %1, %2, %0;" : "+l"(acc) : "l"(a), "l"(b));
}
__device__ __forceinline__ void add2(uint64_t& a, uint64_t b) {
    asm("add.rn.f32x2 %0, %0, %1;" : "+l"(a) : "l"(b));
}
__device__ __forceinline__ uint64_t pack2(float lo, float hi) {
    uint64_t r; asm("mov.b64 %0, {%1, %2};" : "=l"(r) : "f"(lo), "f"(hi)); return r;
}
__device__ __forceinline__ float2 unpack2(uint64_t v) {
    float2 r; asm("mov.b64 {%0, %1}, %2;" : "=f"(r.x), "=f"(r.y) : "l"(v)); return r;
}

#define FMA4(ACC, S, W) do { \
    (ACC).x = fmaf((S), (W).x, (ACC).x); \
    (ACC).y = fmaf((S), (W).y, (ACC).y); \
    (ACC).z = fmaf((S), (W).z, (ACC).z); \
    (ACC).w = fmaf((S), (W).w, (ACC).w); } while (0)

// interleaved global col gi = pair_glob*8 + o, o = gate*2 + jj (f0 f1 i0 i1 z0 z1 r0 r1)
__device__ __forceinline__ float w_elem(int gi, int d,
                                        const float* __restrict__ kfiz,
                                        const float* __restrict__ kr)
{
    int pairg = gi >> 3, o = gi & 7;
    int gate = o >> 1, jj = o & 1;
    int unit = pairg * 2 + jj;
    return (gate < 3) ? kfiz[(size_t)d * 768 + gate * HH + unit]
                      : kr[(size_t)d * HH + unit];
}
__device__ __forceinline__ float b_elem(int gi,
                                        const float* __restrict__ bfiz,
                                        const float* __restrict__ br)
{
    int pairg = gi >> 3, o = gi & 7;
    int gate = o >> 1, jj = o & 1;
    int unit = pairg * 2 + jj;
    return (gate < 3) ? bfiz[gate * HH + unit] : br[unit];
}

// =============== pre-pass: P = u_t @ W_u + bias ===============
// P[t][blk = bg*16 + cg][ (b&15)*64 + pl*8 + o ]
__global__ void __launch_bounds__(256, 1)
pre_kernel(const float* __restrict__ u, const float* __restrict__ kfiz,
           const float* __restrict__ bfiz, const float* __restrict__ kr,
           const float* __restrict__ br)
{
    extern __shared__ float sm[];
    float* u_sh = sm;             // 8192 floats
    float* W_sh = sm + 128 * 64;  // 32768 floats  [d][512 interleaved cols]

    const int t = blockIdx.x, ch = blockIdx.y, tid = threadIdx.x;

    #pragma unroll
    for (int j = 0; j < 8; ++j) {
        int idx4 = tid + j * 256;
        int b = idx4 >> 4, d4 = (idx4 & 15) << 2;
        *(float4*)&u_sh[b * 64 + d4] =
            *(const float4*)&u[((size_t)b * TT + t) * DD + d4];
    }
    #pragma unroll
    for (int j = 0; j < 128; ++j) {
        int idx = tid + j * 256;
        int d = idx >> 9, cl = idx & 511;
        W_sh[idx] = w_elem(ch * 512 + cl, d, kfiz, kr);
    }
    const int cgid = tid & 127, bh = tid >> 7;
    const int c0 = ch * 512 + cgid * 4;
    float4 bias4;
    bias4.x = b_elem(c0 + 0, bfiz, br);
    bias4.y = b_elem(c0 + 1, bfiz, br);
    bias4.z = b_elem(c0 + 2, bfiz, br);
    bias4.w = b_elem(c0 + 3, bfiz, br);
    __syncthreads();

    const int pair_glob = c0 >> 3, o0 = c0 & 7;    // o0 in {0,4}
    const int cgp = pair_glob >> 3, pl = pair_glob & 7;
    float* pbase = g_P + ((size_t)t * 128 + cgp) * 1024 + pl * 8 + o0;

    for (int bt = 0; bt < 4; ++bt) {
        float4 acc[16];
        #pragma unroll
        for (int ib = 0; ib < 16; ++ib) acc[ib] = bias4;
        #pragma unroll
        for (int dt = 0; dt < 8; ++dt) {
            float4 w[8];
            #pragma unroll
            for (int e = 0; e < 8; ++e)
                w[e] = *(float4*)&W_sh[(dt * 8 + e) * 512 + cgid * 4];
            #pragma unroll
            for (int ib = 0; ib < 16; ++ib) {
                int b = bh * 64 + bt * 16 + ib;
                float4 aA = *(float4*)&u_sh[b * 64 + dt * 8];
                float4 aB = *(float4*)&u_sh[b * 64 + dt * 8 + 4];
                FMA4(acc[ib], aA.x, w[0]); FMA4(acc[ib], aA.y, w[1]);
                FMA4(acc[ib], aA.z, w[2]); FMA4(acc[ib], aA.w, w[3]);
                FMA4(acc[ib], aB.x, w[4]); FMA4(acc[ib], aB.y, w[5]);
                FMA4(acc[ib], aB.z, w[6]); FMA4(acc[ib], aB.w, w[7]);
            }
        }
        #pragma unroll
        for (int ib = 0; ib < 16; ++ib) {
            int b = bh * 64 + bt * 16 + ib;
            *(float4*)(pbase + (size_t)(b >> 4) * (16 * 1024) + (b & 15) * 64) = acc[ib];
        }
    }
}

// =============== serial recurrence, per-thread dataflow ===============
// 128 blocks: cg = bid&15, bg = bid>>4.
// Block (cg,bg): units [cg*16, cg*16+16), batches [bg*16, bg*16+16).
// Thread with k-slice ksl only needs h cols from producer block (ksl, bg):
// poll flag[bg*16+ksl] >= t+1, no block-wide wait.
__global__ void __launch_bounds__(256, 1)
serial_kernel(const float* __restrict__ x0, const float* __restrict__ kfiz,
              const float* __restrict__ kr)
{
    extern __shared__ float sm[];
    float* part = sm;             // [16 ksl][16 b][64 l] = 16384 floats

    const int tid = threadIdx.x, bid = blockIdx.x;
    const int cg = bid & 15, bg = bid >> 4;
    const int ksl = tid >> 4, cq = tid & 15;

    // packed weights: thread covers cols l = cq*4..+3, k rows ksl*16..+15
    uint64_t wp[16][2];
    {
        const int pair_glob = cg * 8 + (cq >> 1);
        const int oh = cq & 1;
        #pragma unroll
        for (int j = 0; j < 16; ++j) {
            float wv[4];
            #pragma unroll
            for (int c = 0; c < 4; ++c) {
                int o = oh * 4 + c, gate = o >> 1, jj = o & 1;
                int unit = pair_glob * 2 + jj;
                int row = DD + ksl * 16 + j;
                wv[c] = (gate < 3) ? kfiz[(size_t)row * 768 + gate * HH + unit]
                                   : kr[(size_t)row * HH + unit];
            }
            wp[j][0] = pack2(wv[0], wv[1]);
            wp[j][1] = pack2(wv[2], wv[3]);
        }
    }

    // c/h ownership (reduce-thread layout): batch br, local unit pl*2+jj
    const int br = tid >> 4, pl = (tid >> 1) & 7, jj = tid & 1;
    const int uloc = pl * 2 + jj;
    float c = x0[(size_t)(bg * 16 + br) * (2 * HH) + HH + cg * 16 + uloc];

    // every block publishes ITS OWN h0 slice: cols cg*16..+16, its 16 batches
    {
        int b0 = tid >> 4, j0 = tid & 15;
        g_hist[(size_t)(bg * 16 + b0) * HH + cg * 16 + j0] =
            x0[(size_t)(bg * 16 + b0) * (2 * HH) + cg * 16 + j0];
    }
    __syncthreads();
    if (tid == 0)
        asm volatile("st.release.gpu.u32 [%0], %1;"
                     :: "l"(&g_flag[bid * 32]), "r"(1u) : "memory");

    const unsigned* myflag = &g_flag[(bg * 16 + ksl) * 32];

#define STEPK(HV, K) do { uint64_t hd_ = pack2((HV), (HV)); \
    fma2(a0_, hd_, wp[K][0]); fma2(a1_, hd_, wp[K][1]); } while (0)

    for (int t = 0; t < TT; ++t) {
        ulonglong2 pvv =
            __ldcg((const ulonglong2*)(g_P + ((size_t)t * 128 + bid) * 1024) + tid);

        // per-thread wait: only my k-slice's producer
        {
            unsigned v;
            do {
                asm volatile("ld.acquire.gpu.u32 %0, [%1];"
                             : "=r"(v) : "l"(myflag) : "memory");
            } while (v < (unsigned)(t + 1));
        }

        const float* hb = g_hist + (size_t)t * (BB * HH)
                        + (size_t)(bg * 16) * HH + ksl * 16;

        #pragma unroll
        for (int b = 0; b < 16; ++b) {
            const float4* hp = (const float4*)(hb + (size_t)b * HH);
            float4 h0 = __ldcg(hp + 0);
            float4 h1 = __ldcg(hp + 1);
            float4 h2 = __ldcg(hp + 2);
            float4 h3 = __ldcg(hp + 3);
            uint64_t a0_ = 0ull, a1_ = 0ull;
            STEPK(h0.x,  0); STEPK(h0.y,  1); STEPK(h0.z,  2); STEPK(h0.w,  3);
            STEPK(h1.x,  4); STEPK(h1.y,  5); STEPK(h1.z,  6); STEPK(h1.w,  7);
            STEPK(h2.x,  8); STEPK(h2.y,  9); STEPK(h2.z, 10); STEPK(h2.w, 11);
            STEPK(h3.x, 12); STEPK(h3.y, 13); STEPK(h3.z, 14); STEPK(h3.w, 15);
            float2 p0 = unpack2(a0_);
            float2 p1 = unpack2(a1_);
            *(float4*)&part[ksl * 1024 + b * 64 + cq * 4] =
                make_float4(p0.x, p0.y, p1.x, p1.y);
        }
        __syncthreads();   // part complete

        // reduce over 16 k-slices (+ P), activate, shfl-exchange, c/h update
        {
            uint64_t s0 = pvv.x, s1 = pvv.y;
            #pragma unroll
            for (int k2 = 0; k2 < 16; ++k2) {
                ulonglong2 q = *(const ulonglong2*)&part[k2 * 1024 + tid * 4];
                add2(s0, q.x); add2(s1, q.y);
            }
            float2 f01 = unpack2(s0), f23 = unpack2(s1);
            float v0 = f01.x, v1 = f01.y, v2 = f23.x, v3 = f23.y;
            if (jj == 0) {             // cols f0 f1 i0 i1
                v0 = sigf(v0); v1 = sigf(v1); v2 = sigf(v2); v3 = sigf(v3);
            } else {                   // cols z0 z1 r0 r1
                v0 = sigf(v0); v1 = sigf(v1);
                v2 = tanh_fast(v2); v3 = tanh_fast(v3);
            }
            // exchange with partner (tid^1): other half of this unit pair's gates
            float o0 = __shfl_xor_sync(0xFFFFFFFFu, v0, 1);
            float o1 = __shfl_xor_sync(0xFFFFFFFFu, v1, 1);
            float o2 = __shfl_xor_sync(0xFFFFFFFFu, v2, 1);
            float o3 = __shfl_xor_sync(0xFFFFFFFFu, v3, 1);
            float f, ii, z, r;
            if (jj == 0) { f = v0; ii = v2; z = o0; r = o2; }   // unit pl*2
            else         { f = o1; ii = o3; z = v1; r = v3; }   // unit pl*2+1
            c = fmaf(f, c, ii * r);
            g_hist[(size_t)(t + 1) * (BB * HH)
                   + (size_t)(bg * 16 + br) * HH + cg * 16 + uloc] = z * tanh_fast(c);
        }
        __syncthreads();   // h stores done + part safe to overwrite
        if (tid == 0)
            asm volatile("st.release.gpu.u32 [%0], %1;"
                         :: "l"(&g_flag[bid * 32]), "r"((unsigned)(t + 2)) : "memory");
    }
#undef STEPK
}

// =============== post-pass: y[b][t][:] = h_t @ W_out + b_out ===============
__global__ void __launch_bounds__(256, 1)
post_kernel(const float* __restrict__ Wout, const float* __restrict__ bout,
            float* __restrict__ out)
{
    extern __shared__ float sm[];
    float* H_sh  = sm;              // [128][264]
    float* W_sh  = sm + 128 * 264;  // [256][32]
    float* bo_sh = W_sh + 256 * 32; // [32]

    const int t = blockIdx.x, tid = threadIdx.x;
    const float* hrow = g_hist + (size_t)(t + 1) * (BB * HH);

    #pragma unroll
    for (int j = 0; j < 32; ++j) {
        int idx4 = tid + j * 256;
        int b = idx4 >> 6, k4 = (idx4 & 63) << 2;
        *(float4*)&H_sh[b * 264 + k4] = __ldcg((const float4*)(hrow + b * HH + k4));
    }
    #pragma unroll
    for (int j = 0; j < 32; ++j) {
        int idx = tid + j * 256;
        W_sh[idx] = Wout[idx];
    }
    if (tid < 32) bo_sh[tid] = bout[tid];
    __syncthreads();

    const int b = tid >> 1, oh = tid & 1;
    float4 acc[4];
    #pragma unroll
    for (int q = 0; q < 4; ++q)
        acc[q] = *(float4*)&bo_sh[oh * 16 + q * 4];

    const float* hb = H_sh + b * 264;
    #pragma unroll 4
    for (int k = 0; k < 256; ++k) {
        float a = hb[k];
        const float* wr = W_sh + k * 32 + oh * 16;
        #pragma unroll
        for (int q = 0; q < 4; ++q) {
            float4 wv = *(const float4*)(wr + q * 4);
            FMA4(acc[q], a, wv);
        }
    }
    float* ob = out + ((size_t)b * TT + t) * OO + oh * 16;
    #pragma unroll
    for (int q = 0; q < 4; ++q) *(float4*)(ob + q * 4) = acc[q];
}

extern "C" void kernel_launch(void* const* d_in, const int* in_sizes, int n_in,
                              void* d_out, int out_size)
{
    const float* u    = (const float*)d_in[0];
    const float* x0   = (const float*)d_in[1];
    const float* kfiz = (const float*)d_in[2];
    const float* bfiz = (const float*)d_in[3];
    const float* kr   = (const float*)d_in[4];
    const float* br   = (const float*)d_in[5];
    const float* Wout = (const float*)d_in[6];
    const float* bout = (const float*)d_in[7];
    float* out = (float*)d_out;

    const size_t preSmem  = (size_t)(128 * 64 + 64 * 512) * sizeof(float);       // 163,840
    const size_t serSmem  = 131072;  // 65,536 used; padded to force 1 block/SM
    const size_t postSmem = (size_t)(128 * 264 + 256 * 32 + 32) * sizeof(float); // 168,064

    cudaFuncSetAttribute(pre_kernel,    cudaFuncAttributeMaxDynamicSharedMemorySize, (int)preSmem);
    cudaFuncSetAttribute(serial_kernel, cudaFuncAttributeMaxDynamicSharedMemorySize, (int)serSmem);
    cudaFuncSetAttribute(post_kernel,   cudaFuncAttributeMaxDynamicSharedMemorySize, (int)postSmem);

    reset_kernel<<<1, 256>>>();
    pre_kernel<<<dim3(TT, 2), NTHR, preSmem>>>(u, kfiz, bfiz, kr, br);
    serial_kernel<<<NBLK, NTHR, serSmem>>>(x0, kfiz, kr);
    post_kernel<<<TT, NTHR, postSmem>>>(Wout, bout, out);
}

// round 13
// speedup vs baseline: 1.1079x; 1.1079x over previous
#include <cuda_runtime.h>
#include <cstdint>

#define BB   128
#define TT   2048
#define DD   64
#define HH   256
#define OO   32
#define NBLK 128
#define NTHR 256

// ---- static device scratch (no allocations) ----
__device__ float    g_P[(size_t)TT * BB * 1024];          // [t][blk=bg*16+cg][b16*64+l] (1 GiB)
__device__ float    g_hist[(size_t)(TT + 1) * BB * HH];   // [t][b][k]
__device__ unsigned g_flag[NBLK * 32];                    // one flag per block, 128B apart

__global__ void reset_kernel() {
    for (int i = threadIdx.x; i < NBLK * 32; i += 256) g_flag[i] = 0u;
}

__device__ __forceinline__ float sigf(float x) {
    return 1.0f / (1.0f + __expf(-x));
}
__device__ __forceinline__ float tanh_fast(float x) {
    return 1.0f - 2.0f / (__expf(2.0f * x) + 1.0f);
}

__device__ __forceinline__ void fma2(uint64_t& acc, uint64_t a, uint64_t b) {
    asm("fma.rn.f32x2 %0, %1, %2, %0;" : "+l"(acc) : "l"(a), "l"(b));
}
__device__ __forceinline__ void add2(uint64_t& a, uint64_t b) {
    asm("add.rn.f32x2 %0, %0, %1;" : "+l"(a) : "l"(b));
}
__device__ __forceinline__ uint64_t pack2(float lo, float hi) {
    uint64_t r; asm("mov.b64 %0, {%1, %2};" : "=l"(r) : "f"(lo), "f"(hi)); return r;
}
__device__ __forceinline__ float2 unpack2(uint64_t v) {
    float2 r; asm("mov.b64 {%0, %1}, %2;" : "=f"(r.x), "=f"(r.y) : "l"(v)); return r;
}

#define FMA4(ACC, S, W) do { \
    (ACC).x = fmaf((S), (W).x, (ACC).x); \
    (ACC).y = fmaf((S), (W).y, (ACC).y); \
    (ACC).z = fmaf((S), (W).z, (ACC).z); \
    (ACC).w = fmaf((S), (W).w, (ACC).w); } while (0)

// interleaved global col gi = pair_glob*8 + o, o = gate*2 + jj (f0 f1 i0 i1 z0 z1 r0 r1)
__device__ __forceinline__ float w_elem(int gi, int d,
                                        const float* __restrict__ kfiz,
                                        const float* __restrict__ kr)
{
    int pairg = gi >> 3, o = gi & 7;
    int gate = o >> 1, jj = o & 1;
    int unit = pairg * 2 + jj;
    return (gate < 3) ? kfiz[(size_t)d * 768 + gate * HH + unit]
                      : kr[(size_t)d * HH + unit];
}
__device__ __forceinline__ float b_elem(int gi,
                                        const float* __restrict__ bfiz,
                                        const float* __restrict__ br)
{
    int pairg = gi >> 3, o = gi & 7;
    int gate = o >> 1, jj = o & 1;
    int unit = pairg * 2 + jj;
    return (gate < 3) ? bfiz[gate * HH + unit] : br[unit];
}

// =============== pre-pass: P = u_t @ W_u + bias ===============
// P[t][blk = bg*16 + cg][ (b&15)*64 + pl*8 + o ]
__global__ void __launch_bounds__(256, 1)
pre_kernel(const float* __restrict__ u, const float* __restrict__ kfiz,
           const float* __restrict__ bfiz, const float* __restrict__ kr,
           const float* __restrict__ br)
{
    extern __shared__ float sm[];
    float* u_sh = sm;             // 8192 floats
    float* W_sh = sm + 128 * 64;  // 32768 floats  [d][512 interleaved cols]

    const int t = blockIdx.x, ch = blockIdx.y, tid = threadIdx.x;

    #pragma unroll
    for (int j = 0; j < 8; ++j) {
        int idx4 = tid + j * 256;
        int b = idx4 >> 4, d4 = (idx4 & 15) << 2;
        *(float4*)&u_sh[b * 64 + d4] =
            *(const float4*)&u[((size_t)b * TT + t) * DD + d4];
    }
    #pragma unroll
    for (int j = 0; j < 128; ++j) {
        int idx = tid + j * 256;
        int d = idx >> 9, cl = idx & 511;
        W_sh[idx] = w_elem(ch * 512 + cl, d, kfiz, kr);
    }
    const int cgid = tid & 127, bh = tid >> 7;
    const int c0 = ch * 512 + cgid * 4;
    float4 bias4;
    bias4.x = b_elem(c0 + 0, bfiz, br);
    bias4.y = b_elem(c0 + 1, bfiz, br);
    bias4.z = b_elem(c0 + 2, bfiz, br);
    bias4.w = b_elem(c0 + 3, bfiz, br);
    __syncthreads();

    const int pair_glob = c0 >> 3, o0 = c0 & 7;    // o0 in {0,4}
    const int cgp = pair_glob >> 3, pl = pair_glob & 7;
    float* pbase = g_P + ((size_t)t * 128 + cgp) * 1024 + pl * 8 + o0;

    for (int bt = 0; bt < 4; ++bt) {
        float4 acc[16];
        #pragma unroll
        for (int ib = 0; ib < 16; ++ib) acc[ib] = bias4;
        #pragma unroll
        for (int dt = 0; dt < 8; ++dt) {
            float4 w[8];
            #pragma unroll
            for (int e = 0; e < 8; ++e)
                w[e] = *(float4*)&W_sh[(dt * 8 + e) * 512 + cgid * 4];
            #pragma unroll
            for (int ib = 0; ib < 16; ++ib) {
                int b = bh * 64 + bt * 16 + ib;
                float4 aA = *(float4*)&u_sh[b * 64 + dt * 8];
                float4 aB = *(float4*)&u_sh[b * 64 + dt * 8 + 4];
                FMA4(acc[ib], aA.x, w[0]); FMA4(acc[ib], aA.y, w[1]);
                FMA4(acc[ib], aA.z, w[2]); FMA4(acc[ib], aA.w, w[3]);
                FMA4(acc[ib], aB.x, w[4]); FMA4(acc[ib], aB.y, w[5]);
                FMA4(acc[ib], aB.z, w[6]); FMA4(acc[ib], aB.w, w[7]);
            }
        }
        #pragma unroll
        for (int ib = 0; ib < 16; ++ib) {
            int b = bh * 64 + bt * 16 + ib;
            *(float4*)(pbase + (size_t)(b >> 4) * (16 * 1024) + (b & 15) * 64) = acc[ib];
        }
    }
}

// =============== serial recurrence ===============
// 128 blocks: cg = bid&15, bg = bid>>4.
// Block (cg,bg): units [cg*16, cg*16+16), batches [bg*16, bg*16+16).
// Per step: wait 16 producer flags (relaxed poll), stage h[t] (16KB) into smem
// cooperatively, GEMM from smem broadcast, reduce, update, publish flag.
__global__ void __launch_bounds__(256, 1)
serial_kernel(const float* __restrict__ x0, const float* __restrict__ kfiz,
              const float* __restrict__ kr)
{
    extern __shared__ float sm[];
    float* part = sm;             // [16 ksl][16 b][64 l] = 16384 floats
    float* hs   = sm + 16384;     // [16 b][256 k]        = 4096 floats

    const int tid = threadIdx.x, bid = blockIdx.x;
    const int cg = bid & 15, bg = bid >> 4;
    const int ksl = tid >> 4, cq = tid & 15;

    // packed weights: thread covers cols l = cq*4..+3, k rows ksl*16..+15
    uint64_t wp[16][2];
    {
        const int pair_glob = cg * 8 + (cq >> 1);
        const int oh = cq & 1;
        #pragma unroll
        for (int j = 0; j < 16; ++j) {
            float wv[4];
            #pragma unroll
            for (int c = 0; c < 4; ++c) {
                int o = oh * 4 + c, gate = o >> 1, jj = o & 1;
                int unit = pair_glob * 2 + jj;
                int row = DD + ksl * 16 + j;
                wv[c] = (gate < 3) ? kfiz[(size_t)row * 768 + gate * HH + unit]
                                   : kr[(size_t)row * HH + unit];
            }
            wp[j][0] = pack2(wv[0], wv[1]);
            wp[j][1] = pack2(wv[2], wv[3]);
        }
    }

    // c/h ownership (reduce-thread layout): batch br, local unit pl*2+jj
    const int br = tid >> 4, pl = (tid >> 1) & 7, jj = tid & 1;
    const int uloc = pl * 2 + jj;
    float c = x0[(size_t)(bg * 16 + br) * (2 * HH) + HH + cg * 16 + uloc];

    // every block publishes ITS OWN h0 slice: cols cg*16..+16, its 16 batches
    {
        int b0 = tid >> 4, j0 = tid & 15;
        g_hist[(size_t)(bg * 16 + b0) * HH + cg * 16 + j0] =
            x0[(size_t)(bg * 16 + b0) * (2 * HH) + cg * 16 + j0];
    }
    __syncthreads();
    if (tid == 0)
        asm volatile("st.release.gpu.u32 [%0], %1;"
                     :: "l"(&g_flag[bid * 32]), "r"(1u) : "memory");

#define STEPK(HV, K) do { uint64_t hd_ = pack2((HV), (HV)); \
    fma2(a0_, hd_, wp[K][0]); fma2(a1_, hd_, wp[K][1]); } while (0)

    for (int t = 0; t < TT; ++t) {
        ulonglong2 pvv =
            __ldcg((const ulonglong2*)(g_P + ((size_t)t * 128 + bid) * 1024) + tid);

        // block-wide wait: 16 threads poll the 16 producers (relaxed; safety:
        // producers use st.release so h-stores precede flag value in L2, and
        // the h lines are fresh write-once lines read via __ldcg below).
        if (tid < 16) {
            const unsigned* fp = &g_flag[(bg * 16 + tid) * 32];
            unsigned v;
            do {
                asm volatile("ld.relaxed.gpu.u32 %0, [%1];"
                             : "=r"(v) : "l"(fp) : "memory");
            } while (v < (unsigned)(t + 1));
        }
        __syncthreads();

        // cooperative stage of h[t] for this bg: 4096 contiguous floats
        {
            const float4* hsrc = (const float4*)(g_hist + (size_t)t * (BB * HH)
                                                 + (size_t)(bg * 16) * HH);
            float4 v0 = __ldcg(hsrc + tid);
            float4 v1 = __ldcg(hsrc + tid + 256);
            float4 v2 = __ldcg(hsrc + tid + 512);
            float4 v3 = __ldcg(hsrc + tid + 768);
            ((float4*)hs)[tid]       = v0;
            ((float4*)hs)[tid + 256] = v1;
            ((float4*)hs)[tid + 512] = v2;
            ((float4*)hs)[tid + 768] = v3;
        }
        __syncthreads();

        // GEMM: h from smem (broadcast LDS), weights in registers
        #pragma unroll
        for (int b = 0; b < 16; ++b) {
            const float4* hp = (const float4*)(hs + b * 256 + ksl * 16);
            float4 h0 = hp[0], h1 = hp[1], h2 = hp[2], h3 = hp[3];
            uint64_t a0_ = 0ull, a1_ = 0ull;
            STEPK(h0.x,  0); STEPK(h0.y,  1); STEPK(h0.z,  2); STEPK(h0.w,  3);
            STEPK(h1.x,  4); STEPK(h1.y,  5); STEPK(h1.z,  6); STEPK(h1.w,  7);
            STEPK(h2.x,  8); STEPK(h2.y,  9); STEPK(h2.z, 10); STEPK(h2.w, 11);
            STEPK(h3.x, 12); STEPK(h3.y, 13); STEPK(h3.z, 14); STEPK(h3.w, 15);
            float2 p0 = unpack2(a0_);
            float2 p1 = unpack2(a1_);
            *(float4*)&part[ksl * 1024 + b * 64 + cq * 4] =
                make_float4(p0.x, p0.y, p1.x, p1.y);
        }
        __syncthreads();   // part complete

        // reduce over 16 k-slices (+ P), activate, shfl-exchange, c/h update
        {
            uint64_t s0 = pvv.x, s1 = pvv.y;
            #pragma unroll
            for (int k2 = 0; k2 < 16; ++k2) {
                ulonglong2 q = *(const ulonglong2*)&part[k2 * 1024 + tid * 4];
                add2(s0, q.x); add2(s1, q.y);
            }
            float2 f01 = unpack2(s0), f23 = unpack2(s1);
            float v0 = f01.x, v1 = f01.y, v2 = f23.x, v3 = f23.y;
            if (jj == 0) {             // cols f0 f1 i0 i1
                v0 = sigf(v0); v1 = sigf(v1); v2 = sigf(v2); v3 = sigf(v3);
            } else {                   // cols z0 z1 r0 r1
                v0 = sigf(v0); v1 = sigf(v1);
                v2 = tanh_fast(v2); v3 = tanh_fast(v3);
            }
            float o0 = __shfl_xor_sync(0xFFFFFFFFu, v0, 1);
            float o1 = __shfl_xor_sync(0xFFFFFFFFu, v1, 1);
            float o2 = __shfl_xor_sync(0xFFFFFFFFu, v2, 1);
            float o3 = __shfl_xor_sync(0xFFFFFFFFu, v3, 1);
            float f, ii, z, r;
            if (jj == 0) { f = v0; ii = v2; z = o0; r = o2; }   // unit pl*2
            else         { f = o1; ii = o3; z = v1; r = v3; }   // unit pl*2+1
            c = fmaf(f, c, ii * r);
            g_hist[(size_t)(t + 1) * (BB * HH)
                   + (size_t)(bg * 16 + br) * HH + cg * 16 + uloc] = z * tanh_fast(c);
        }
        __syncthreads();   // h stores issued + part reads done
        if (tid == 0)
            asm volatile("st.release.gpu.u32 [%0], %1;"
                         :: "l"(&g_flag[bid * 32]), "r"((unsigned)(t + 2)) : "memory");
    }
#undef STEPK
}

// =============== post-pass: y[b][t][:] = h_t @ W_out + b_out ===============
__global__ void __launch_bounds__(256, 1)
post_kernel(const float* __restrict__ Wout, const float* __restrict__ bout,
            float* __restrict__ out)
{
    extern __shared__ float sm[];
    float* H_sh  = sm;              // [128][264]
    float* W_sh  = sm + 128 * 264;  // [256][32]
    float* bo_sh = W_sh + 256 * 32; // [32]

    const int t = blockIdx.x, tid = threadIdx.x;
    const float* hrow = g_hist + (size_t)(t + 1) * (BB * HH);

    #pragma unroll
    for (int j = 0; j < 32; ++j) {
        int idx4 = tid + j * 256;
        int b = idx4 >> 6, k4 = (idx4 & 63) << 2;
        *(float4*)&H_sh[b * 264 + k4] = __ldcg((const float4*)(hrow + b * HH + k4));
    }
    #pragma unroll
    for (int j = 0; j < 32; ++j) {
        int idx = tid + j * 256;
        W_sh[idx] = Wout[idx];
    }
    if (tid < 32) bo_sh[tid] = bout[tid];
    __syncthreads();

    const int b = tid >> 1, oh = tid & 1;
    float4 acc[4];
    #pragma unroll
    for (int q = 0; q < 4; ++q)
        acc[q] = *(float4*)&bo_sh[oh * 16 + q * 4];

    const float* hb = H_sh + b * 264;
    #pragma unroll 4
    for (int k = 0; k < 256; ++k) {
        float a = hb[k];
        const float* wr = W_sh + k * 32 + oh * 16;
        #pragma unroll
        for (int q = 0; q < 4; ++q) {
            float4 wv = *(const float4*)(wr + q * 4);
            FMA4(acc[q], a, wv);
        }
    }
    float* ob = out + ((size_t)b * TT + t) * OO + oh * 16;
    #pragma unroll
    for (int q = 0; q < 4; ++q) *(float4*)(ob + q * 4) = acc[q];
}

extern "C" void kernel_launch(void* const* d_in, const int* in_sizes, int n_in,
                              void* d_out, int out_size)
{
    const float* u    = (const float*)d_in[0];
    const float* x0   = (const float*)d_in[1];
    const float* kfiz = (const float*)d_in[2];
    const float* bfiz = (const float*)d_in[3];
    const float* kr   = (const float*)d_in[4];
    const float* br   = (const float*)d_in[5];
    const float* Wout = (const float*)d_in[6];
    const float* bout = (const float*)d_in[7];
    float* out = (float*)d_out;

    const size_t preSmem  = (size_t)(128 * 64 + 64 * 512) * sizeof(float);       // 163,840
    const size_t serSmem  = 131072;  // 81,920 used; padded to force 1 block/SM
    const size_t postSmem = (size_t)(128 * 264 + 256 * 32 + 32) * sizeof(float); // 168,064

    cudaFuncSetAttribute(pre_kernel,    cudaFuncAttributeMaxDynamicSharedMemorySize, (int)preSmem);
    cudaFuncSetAttribute(serial_kernel, cudaFuncAttributeMaxDynamicSharedMemorySize, (int)serSmem);
    cudaFuncSetAttribute(post_kernel,   cudaFuncAttributeMaxDynamicSharedMemorySize, (int)postSmem);

    reset_kernel<<<1, 256>>>();
    pre_kernel<<<dim3(TT, 2), NTHR, preSmem>>>(u, kfiz, bfiz, kr, br);
    serial_kernel<<<NBLK, NTHR, serSmem>>>(x0, kfiz, kr);
    post_kernel<<<TT, NTHR, postSmem>>>(Wout, bout, out);
}